// round 13
// baseline (speedup 1.0000x reference)
#include <cuda_runtime.h>
#include <cstdint>

// SpearmanCorrelationLoss: pred/target [N=16384, D=512] fp32.
// Ranks are exact permutations of 1..N per column => mean/std constants;
// loss = -( sum(pr*tr)/(N*D) - mu^2 ) / denom. Only need exact int64 sum
// of rank products. Per-column stable 5-bit LSD radix sort, ballot
// multisplit (meq = shfl(leq, digit)), u64-packed (key|payload) smem
// records, 4-barrier passes, 2-bit final pass. Single fused kernel.

#define NROWS 16384
#define NCOLS 512
#define NTHREADS 1024
#define NWARPS 32
#define SLOTS 16      // items per thread
#define CHUNK 512     // contiguous items per warp
#define HSTRIDE 33    // padded to kill bank conflicts

__device__ unsigned long long g_part[NCOLS];
__device__ unsigned int g_arrive;

__device__ __forceinline__ unsigned int f2sort(float f) {
    unsigned int u = __float_as_uint(f);
    return (u & 0x80000000u) ? ~u : (u | 0x80000000u);
}

struct Smem {
    unsigned long long sdata[NROWS];             // 128 KB: key<<32 | payload
    unsigned int       hist[NWARPS * HSTRIDE];   // 4224 B  [warp*33 + bin]
    unsigned int       binoff[32];
    unsigned long long warp_s[NWARPS];
    int                is_last;
};

// One stable LSD pass over packed sdata (BITS = 5 normally, 2 for final).
// MODE 0: scatter (key|payload) back to smem.
// MODE 1: final pred pass: pos+1 = pred rank; stage target sort directly:
//         sdata[row] = (f2sort(tgt[row,col])<<32) | rank.
// MODE 2: final target pass: accumulate (pos+1)*rank in registers.
template <int MODE, int BITS>
__device__ __forceinline__ unsigned long long
radix_pass(Smem* sm, int shift, int tid, int lane, int warp,
           unsigned int ls0, unsigned int ls1, unsigned int ls2,
           unsigned int ls3, unsigned int ls4,
           const float* __restrict__ tgt, int col) {
    const int chunk = warp * CHUNK;
    const unsigned int ltmask = (1u << lane) - 1u;
    const unsigned int dmask = (1u << BITS) - 1u;

    unsigned int k[SLOTS];
    unsigned int pv[SLOTS];   // low16 = payload (idx or rank), high16 = offset
    #pragma unroll
    for (int s = 0; s < SLOTS; s++) {
        unsigned long long w = sm->sdata[chunk + s * 32 + lane];
        k[s]  = (unsigned int)(w >> 32);
        pv[s] = (unsigned int)w & 0xffffu;
    }

    // ---- Phase A: warp multisplit (leq with loop-invariant lane masks,
    //      meq = shfl(leq, digit)) ----
    unsigned int c = 0;   // running count of digit==lane in this warp
    #pragma unroll
    for (int s = 0; s < SLOTS; s++) {
        unsigned int d  = (k[s] >> shift) & dmask;
        unsigned int b0 = __ballot_sync(0xffffffffu, d & 1u);
        unsigned int b1 = __ballot_sync(0xffffffffu, d & 2u);
        unsigned int leq = (b0 ^ ls0) & (b1 ^ ls1);
        if (BITS > 2) {
            unsigned int b2 = __ballot_sync(0xffffffffu, d & 4u);
            unsigned int b3 = __ballot_sync(0xffffffffu, d & 8u);
            unsigned int b4 = __ballot_sync(0xffffffffu, d & 16u);
            leq &= (b2 ^ ls2) & (b3 ^ ls3) & (b4 ^ ls4);
        }
        unsigned int meq    = __shfl_sync(0xffffffffu, leq, (int)d);
        unsigned int before = __shfl_sync(0xffffffffu, c,   (int)d);
        unsigned int prior  = __popc(meq & ltmask);
        pv[s] |= (before + prior) << 16;
        c += __popc(leq);
    }
    sm->hist[warp * HSTRIDE + lane] = c;   // bins>=2^BITS are just 0
    __syncthreads();

    // ---- Phase B: scan in stable (bin, warp) order, 2 barriers ----
    unsigned int within, myb;
    {
        int b = warp;          // scan-warp == bin
        int w = lane;          // lane == source warp
        unsigned int v = sm->hist[w * HSTRIDE + b];   // lane*33+b: conflict-free
        unsigned int x = v;
        #pragma unroll
        for (int o = 1; o < 32; o <<= 1) {
            unsigned int y = __shfl_up_sync(0xffffffffu, x, o);
            if (w >= o) x += y;
        }
        if (w == 31) sm->binoff[b] = x;   // bin totals
        within = x - v;                   // exclusive within bin b, src warp w
        myb = (unsigned int)b;
    }
    __syncthreads();
    {
        // redundant bin-offset scan in every warp (no warp0 serialization)
        unsigned int t = sm->binoff[lane];
        unsigned int xx = t;
        #pragma unroll
        for (int o = 1; o < 32; o <<= 1) {
            unsigned int y = __shfl_up_sync(0xffffffffu, xx, o);
            if (lane >= o) xx += y;
        }
        unsigned int excl = xx - t;                              // for bin 'lane'
        unsigned int eb = __shfl_sync(0xffffffffu, excl, (int)myb);
        sm->hist[lane * HSTRIDE + myb] = eb + within;            // conflict-free
    }
    __syncthreads();

    // ---- Phase C ----
    unsigned long long acc = 0ull;
    #pragma unroll
    for (int s = 0; s < SLOTS; s++) {
        unsigned int d   = (k[s] >> shift) & dmask;
        unsigned int pos = sm->hist[warp * HSTRIDE + d] + (pv[s] >> 16);
        if (MODE == 0) {
            sm->sdata[pos] = ((unsigned long long)k[s] << 32) | (pv[s] & 0xffffu);
        } else if (MODE == 1) {
            unsigned int row = pv[s] & 0xffffu;
            // rows form a permutation -> no races; sdata fully consumed into
            // registers before the Phase B barriers.
            sm->sdata[row] = ((unsigned long long)f2sort(tgt[(size_t)row * NCOLS + col]) << 32)
                           | (unsigned long long)(pos + 1);   // pred rank
        } else {
            acc += (unsigned long long)(pos + 1) *
                   (unsigned long long)(pv[s] & 0xffffu);
        }
    }
    if (MODE != 2) __syncthreads();
    return acc;
}

__global__ void __launch_bounds__(NTHREADS, 1)
spearman_fused_kernel(const float* __restrict__ pred, const float* __restrict__ tgt,
                      float* __restrict__ out) {
    extern __shared__ char raw[];
    Smem* sm = (Smem*)raw;

    const int col  = blockIdx.x;
    const int tid  = threadIdx.x;
    const int lane = tid & 31;
    const int warp = tid >> 5;

    // loop-invariant lane equality masks: ls_i = (lane bit i) ? 0 : ~0
    const unsigned int ls0 = (lane & 1)  ? 0u : 0xffffffffu;
    const unsigned int ls1 = (lane & 2)  ? 0u : 0xffffffffu;
    const unsigned int ls2 = (lane & 4)  ? 0u : 0xffffffffu;
    const unsigned int ls3 = (lane & 8)  ? 0u : 0xffffffffu;
    const unsigned int ls4 = (lane & 16) ? 0u : 0xffffffffu;

    // stage pred column: payload = row index
    for (int i = tid; i < NROWS; i += NTHREADS)
        sm->sdata[i] = ((unsigned long long)f2sort(pred[(size_t)i * NCOLS + col]) << 32)
                     | (unsigned long long)i;
    __syncthreads();

    // pred sort: 6x 5-bit passes + final 2-bit pass staging the target sort
    for (int p = 0; p < 6; p++)
        radix_pass<0, 5>(sm, p * 5, tid, lane, warp, ls0, ls1, ls2, ls3, ls4, tgt, col);
    radix_pass<1, 2>(sm, 30, tid, lane, warp, ls0, ls1, ls2, ls3, ls4, tgt, col);

    // target sort: 6x 5-bit passes + final 2-bit register-resident dot pass
    for (int p = 0; p < 6; p++)
        radix_pass<0, 5>(sm, p * 5, tid, lane, warp, ls0, ls1, ls2, ls3, ls4, tgt, col);
    unsigned long long s =
        radix_pass<2, 2>(sm, 30, tid, lane, warp, ls0, ls1, ls2, ls3, ls4, tgt, col);

    // block reduce exact int64 dot
    #pragma unroll
    for (int o = 16; o > 0; o >>= 1)
        s += __shfl_down_sync(0xffffffffu, s, o);
    if (lane == 0) sm->warp_s[warp] = s;
    __syncthreads();
    if (warp == 0) {
        s = (lane < NWARPS) ? sm->warp_s[lane] : 0ull;
        #pragma unroll
        for (int o = 16; o > 0; o >>= 1)
            s += __shfl_down_sync(0xffffffffu, s, o);
        if (lane == 0) g_part[col] = s;
    }

    // ---- grid-wide completion: last CTA finalizes ----
    if (tid == 0) {
        __threadfence();
        unsigned int t = atomicAdd(&g_arrive, 1u);
        sm->is_last = (t == (unsigned)(NCOLS - 1));
    }
    __syncthreads();
    if (!sm->is_last) return;

    __threadfence();                 // acquire: all g_part writes visible
    if (tid == 0) g_arrive = 0u;     // reset for next graph replay

    unsigned long long s2 = (tid < NCOLS) ? g_part[tid] : 0ull;
    #pragma unroll
    for (int o = 16; o > 0; o >>= 1)
        s2 += __shfl_down_sync(0xffffffffu, s2, o);
    if (lane == 0) sm->warp_s[warp] = s2;
    __syncthreads();
    if (warp == 0) {
        s2 = (lane < NWARPS) ? sm->warp_s[lane] : 0ull;
        #pragma unroll
        for (int o = 16; o > 0; o >>= 1)
            s2 += __shfl_down_sync(0xffffffffu, s2, o);
        if (lane == 0) {
            const double Nd = (double)NROWS;
            const double Dd = (double)NCOLS;
            const double mu = (Nd + 1.0) * 0.5;
            const double var = (Nd * Nd - 1.0) / 12.0;
            const double sd = sqrt(var + 1e-6);
            const double denom = sd * sd + 1e-6;
            const double mean_pt = (double)s2 / (Nd * Dd);
            const double corr_mean = (mean_pt - mu * mu) / denom;
            out[0] = (float)(-corr_mean);
        }
    }
}

extern "C" void kernel_launch(void* const* d_in, const int* in_sizes, int n_in,
                              void* d_out, int out_size) {
    const float* pred = (const float*)d_in[0];
    const float* tgt  = (const float*)d_in[1];
    float* out = (float*)d_out;

    const int smem_bytes = (int)sizeof(Smem);
    cudaFuncSetAttribute(spearman_fused_kernel,
                         cudaFuncAttributeMaxDynamicSharedMemorySize, smem_bytes);

    spearman_fused_kernel<<<NCOLS, NTHREADS, smem_bytes>>>(pred, tgt, out);
}

// round 14
// speedup vs baseline: 1.0684x; 1.0684x over previous
#include <cuda_runtime.h>
#include <cstdint>

// SpearmanCorrelationLoss: pred/target [N=16384, D=512] fp32.
// Ranks are exact permutations of 1..N => mean/std constants; only need the
// exact int64 sum of rank products.
// Per-column sort = value-binned counting sort (monotone linear binning on
// the float value, 16384 bins) + atomic scatter + exact per-bin insertion
// cleanup on packed u64 (key32|row14|payload14). One scatter pass per sort
// instead of 7 radix passes. Single fused kernel; last CTA finalizes.

#define NROWS 16384
#define NCOLS 512
#define NTHREADS 1024
#define NWARPS 32
#define SLOTS 16          // items per thread
#define NB 16384          // value bins
#define BPT (NB / NTHREADS)   // bins per thread = 16

__device__ unsigned long long g_part[NCOLS];
__device__ unsigned int g_arrive;

__device__ __forceinline__ unsigned int f2sort(float f) {
    unsigned int u = __float_as_uint(f);
    return (u & 0x80000000u) ? ~u : (u | 0x80000000u);
}
__device__ __forceinline__ float sort2f(unsigned int k) {
    unsigned int u = (k & 0x80000000u) ? (k & 0x7fffffffu) : ~k;
    return __uint_as_float(u);
}
__device__ __forceinline__ int valbin(float x) {
    // monotone: floor of increasing linear map; clamp to [0, NB-1]
    float t = (x + 5.5f) * (16384.0f / 11.0f);
    int b = __float2int_rd(t);
    return min(max(b, 0), NB - 1);
}

struct Smem {
    unsigned long long sdata[NROWS];   // 128 KB: key<<32 | row<<14 | payload14
    unsigned int       hist[NB];       // 64 KB
    unsigned int       wscan[NWARPS];
    unsigned long long warp_s[NWARPS];
    int                is_last;
};

// exclusive scan of hist[NB] in place (thread t owns bins [16t,16t+16))
__device__ __forceinline__ void scan_hist(Smem* sm, int tid, int lane, int warp) {
    uint4* hv = (uint4*)(sm->hist + tid * BPT);
    uint4 h0 = hv[0], h1 = hv[1], h2 = hv[2], h3 = hv[3];
    unsigned int l[16] = {h0.x, h0.y, h0.z, h0.w, h1.x, h1.y, h1.z, h1.w,
                          h2.x, h2.y, h2.z, h2.w, h3.x, h3.y, h3.z, h3.w};
    unsigned int tot = 0;
    #pragma unroll
    for (int i = 0; i < 16; i++) { unsigned int v = l[i]; l[i] = tot; tot += v; }
    // warp inclusive scan of thread totals
    unsigned int x = tot;
    #pragma unroll
    for (int o = 1; o < 32; o <<= 1) {
        unsigned int y = __shfl_up_sync(0xffffffffu, x, o);
        if (lane >= o) x += y;
    }
    if (lane == 31) sm->wscan[warp] = x;
    __syncthreads();
    // redundant scan of 32 warp totals in every warp
    unsigned int wt = sm->wscan[lane];
    unsigned int wx = wt;
    #pragma unroll
    for (int o = 1; o < 32; o <<= 1) {
        unsigned int y = __shfl_up_sync(0xffffffffu, wx, o);
        if (lane >= o) wx += y;
    }
    unsigned int wexcl = __shfl_sync(0xffffffffu, wx - wt, warp);
    unsigned int base = wexcl + (x - tot);
    #pragma unroll
    for (int i = 0; i < 16; i++) l[i] += base;
    hv[0] = make_uint4(l[0], l[1], l[2], l[3]);
    hv[1] = make_uint4(l[4], l[5], l[6], l[7]);
    hv[2] = make_uint4(l[8], l[9], l[10], l[11]);
    hv[3] = make_uint4(l[12], l[13], l[14], l[15]);
    __syncthreads();
}

// cleanup: restore exact order within each bin (hist[b] = end offset of bin b)
__device__ __forceinline__ void cleanup(Smem* sm, int tid) {
    const int b0 = tid * BPT;
    unsigned int st = (b0 == 0) ? 0u : sm->hist[b0 - 1];
    #pragma unroll
    for (int bb = 0; bb < BPT; bb++) {
        unsigned int en = sm->hist[b0 + bb];
        for (unsigned int i = st + 1; i < en; i++) {
            unsigned long long v = sm->sdata[i];
            unsigned int j = i;
            while (j > st && sm->sdata[j - 1] > v) {
                sm->sdata[j] = sm->sdata[j - 1];
                j--;
            }
            sm->sdata[j] = v;
        }
        st = en;
    }
}

__global__ void __launch_bounds__(NTHREADS, 1)
spearman_fused_kernel(const float* __restrict__ pred, const float* __restrict__ tgt,
                      float* __restrict__ out) {
    extern __shared__ char raw[];
    Smem* sm = (Smem*)raw;

    const int col  = blockIdx.x;
    const int tid  = threadIdx.x;
    const int lane = tid & 31;
    const int warp = tid >> 5;

    // ---- Phase 1: zero hist ----
    {
        uint4 z = make_uint4(0, 0, 0, 0);
        uint4* hv = (uint4*)(sm->hist + tid * BPT);
        hv[0] = z; hv[1] = z; hv[2] = z; hv[3] = z;
    }
    __syncthreads();

    // ---- Phase 2: load pred, histogram, stash records in regs ----
    unsigned long long e[SLOTS];
    #pragma unroll
    for (int s = 0; s < SLOTS; s++) {
        int row = tid + s * NTHREADS;
        float x = pred[(size_t)row * NCOLS + col];
        unsigned int key = f2sort(x);
        int b = valbin(x);
        e[s] = ((unsigned long long)key << 32) | ((unsigned long long)row << 14);
        atomicAdd(&sm->hist[b], 1u);
    }
    __syncthreads();

    // ---- Phase 3: exclusive scan ----
    scan_hist(sm, tid, lane, warp);

    // ---- Phase 4: scatter (atomic per-bin offsets) ----
    #pragma unroll
    for (int s = 0; s < SLOTS; s++) {
        int b = valbin(sort2f((unsigned int)(e[s] >> 32)));
        unsigned int pos = atomicAdd(&sm->hist[b], 1u);
        sm->sdata[pos] = e[s];
    }
    __syncthreads();

    // ---- Phase 5: cleanup (exact per-bin order: key, then row) ----
    cleanup(sm, tid);
    __syncthreads();

    // ---- Phase 6: read sorted pred (row, rank0) to regs; re-zero hist ----
    unsigned int rr[SLOTS];   // row<<16 | rank0
    #pragma unroll
    for (int s = 0; s < SLOTS; s++) {
        int p = tid + s * NTHREADS;
        unsigned long long w = sm->sdata[p];
        unsigned int row = (unsigned int)(w >> 14) & 0x3fffu;
        rr[s] = (row << 16) | (unsigned int)p;
    }
    {
        uint4 z = make_uint4(0, 0, 0, 0);
        uint4* hv = (uint4*)(sm->hist + tid * BPT);
        hv[0] = z; hv[1] = z; hv[2] = z; hv[3] = z;
    }
    __syncthreads();

    // ---- Phase 7: stage target records (payload = pred rank0), histogram ----
    #pragma unroll
    for (int s = 0; s < SLOTS; s++) {
        unsigned int row   = rr[s] >> 16;
        unsigned int rank0 = rr[s] & 0xffffu;
        float x = tgt[(size_t)row * NCOLS + col];
        unsigned int key = f2sort(x);
        int b = valbin(x);
        sm->sdata[row] = ((unsigned long long)key << 32)
                       | ((unsigned long long)row << 14)
                       | (unsigned long long)rank0;
        atomicAdd(&sm->hist[b], 1u);
    }
    __syncthreads();

    // ---- Phase 8: scan ----
    scan_hist(sm, tid, lane, warp);

    // ---- Phase 9: load + scatter target records ----
    #pragma unroll
    for (int s = 0; s < SLOTS; s++)
        e[s] = sm->sdata[tid + s * NTHREADS];
    __syncthreads();
    #pragma unroll
    for (int s = 0; s < SLOTS; s++) {
        int b = valbin(sort2f((unsigned int)(e[s] >> 32)));
        unsigned int pos = atomicAdd(&sm->hist[b], 1u);
        sm->sdata[pos] = e[s];
    }
    __syncthreads();

    // ---- Phase 10: cleanup (ties by row => matches stable argsort) ----
    cleanup(sm, tid);
    __syncthreads();

    // ---- Phase 11: exact int64 dot ----
    unsigned long long s64 = 0ull;
    #pragma unroll
    for (int s = 0; s < SLOTS; s++) {
        int p = tid + s * NTHREADS;
        unsigned long long w = sm->sdata[p];
        unsigned int rank0 = (unsigned int)w & 0x3fffu;
        s64 += (unsigned long long)(p + 1) * (unsigned long long)(rank0 + 1);
    }
    #pragma unroll
    for (int o = 16; o > 0; o >>= 1)
        s64 += __shfl_down_sync(0xffffffffu, s64, o);
    if (lane == 0) sm->warp_s[warp] = s64;
    __syncthreads();
    if (warp == 0) {
        s64 = (lane < NWARPS) ? sm->warp_s[lane] : 0ull;
        #pragma unroll
        for (int o = 16; o > 0; o >>= 1)
            s64 += __shfl_down_sync(0xffffffffu, s64, o);
        if (lane == 0) g_part[col] = s64;
    }

    // ---- grid-wide completion: last CTA finalizes ----
    if (tid == 0) {
        __threadfence();
        unsigned int t = atomicAdd(&g_arrive, 1u);
        sm->is_last = (t == (unsigned)(NCOLS - 1));
    }
    __syncthreads();
    if (!sm->is_last) return;

    __threadfence();                 // acquire: all g_part writes visible
    if (tid == 0) g_arrive = 0u;     // reset for next graph replay

    unsigned long long s2 = (tid < NCOLS) ? g_part[tid] : 0ull;
    #pragma unroll
    for (int o = 16; o > 0; o >>= 1)
        s2 += __shfl_down_sync(0xffffffffu, s2, o);
    if (lane == 0) sm->warp_s[warp] = s2;
    __syncthreads();
    if (warp == 0) {
        s2 = (lane < NWARPS) ? sm->warp_s[lane] : 0ull;
        #pragma unroll
        for (int o = 16; o > 0; o >>= 1)
            s2 += __shfl_down_sync(0xffffffffu, s2, o);
        if (lane == 0) {
            const double Nd = (double)NROWS;
            const double Dd = (double)NCOLS;
            const double mu = (Nd + 1.0) * 0.5;
            const double var = (Nd * Nd - 1.0) / 12.0;
            const double sd = sqrt(var + 1e-6);
            const double denom = sd * sd + 1e-6;
            const double mean_pt = (double)s2 / (Nd * Dd);
            const double corr_mean = (mean_pt - mu * mu) / denom;
            out[0] = (float)(-corr_mean);
        }
    }
}

extern "C" void kernel_launch(void* const* d_in, const int* in_sizes, int n_in,
                              void* d_out, int out_size) {
    const float* pred = (const float*)d_in[0];
    const float* tgt  = (const float*)d_in[1];
    float* out = (float*)d_out;

    const int smem_bytes = (int)sizeof(Smem);
    cudaFuncSetAttribute(spearman_fused_kernel,
                         cudaFuncAttributeMaxDynamicSharedMemorySize, smem_bytes);

    spearman_fused_kernel<<<NCOLS, NTHREADS, smem_bytes>>>(pred, tgt, out);
}

// round 16
// speedup vs baseline: 1.6631x; 1.5567x over previous
#include <cuda_runtime.h>
#include <cstdint>

// SpearmanCorrelationLoss: pred/target [N=16384, D=512] fp32.
// Ranks are exact permutations of 1..N => mean/std constants; only need the
// exact int64 sum of rank products.
// Per-column: value-binned grouping (monotone linear binning, 16384 bins,
// atomic scatter) + per-element EXACT rank = binstart + #(smaller in bin),
// computed with independent smem loads (no physical sort, no cleanup chains).
// Pred rank rides in the target record (key32|row14|rank14). Single fused
// kernel; last CTA finalizes.

#define NROWS 16384
#define NCOLS 512
#define NTHREADS 1024
#define NWARPS 32
#define SLOTS 16          // items per thread
#define NB 16384          // value bins
#define BPT (NB / NTHREADS)   // bins per thread = 16

__device__ unsigned long long g_part[NCOLS];
__device__ unsigned int g_arrive;

__device__ __forceinline__ unsigned int f2sort(float f) {
    unsigned int u = __float_as_uint(f);
    return (u & 0x80000000u) ? ~u : (u | 0x80000000u);
}
__device__ __forceinline__ int valbin(float x) {
    // monotone: floor of increasing linear map; clamp to [0, NB-1]
    float t = (x + 5.5f) * (16384.0f / 11.0f);
    int b = __float2int_rd(t);
    return min(max(b, 0), NB - 1);
}

struct Smem {
    unsigned long long sdata[NROWS];   // 128 KB: records grouped by bin
    unsigned int       hist[NB];       // 64 KB
    unsigned int       wscan[NWARPS];
    unsigned long long warp_s[NWARPS];
    int                is_last;
};

__device__ __forceinline__ void zero_hist(Smem* sm, int tid) {
    uint4 z = make_uint4(0, 0, 0, 0);
    uint4* hv = (uint4*)(sm->hist + tid * BPT);
    hv[0] = z; hv[1] = z; hv[2] = z; hv[3] = z;
}

// exclusive scan of hist[NB] in place (thread t owns bins [16t,16t+16))
__device__ __forceinline__ void scan_hist(Smem* sm, int tid, int lane, int warp) {
    uint4* hv = (uint4*)(sm->hist + tid * BPT);
    uint4 h0 = hv[0], h1 = hv[1], h2 = hv[2], h3 = hv[3];
    unsigned int l[16] = {h0.x, h0.y, h0.z, h0.w, h1.x, h1.y, h1.z, h1.w,
                          h2.x, h2.y, h2.z, h2.w, h3.x, h3.y, h3.z, h3.w};
    unsigned int tot = 0;
    #pragma unroll
    for (int i = 0; i < 16; i++) { unsigned int v = l[i]; l[i] = tot; tot += v; }
    unsigned int x = tot;
    #pragma unroll
    for (int o = 1; o < 32; o <<= 1) {
        unsigned int y = __shfl_up_sync(0xffffffffu, x, o);
        if (lane >= o) x += y;
    }
    if (lane == 31) sm->wscan[warp] = x;
    __syncthreads();
    unsigned int wt = sm->wscan[lane];
    unsigned int wx = wt;
    #pragma unroll
    for (int o = 1; o < 32; o <<= 1) {
        unsigned int y = __shfl_up_sync(0xffffffffu, wx, o);
        if (lane >= o) wx += y;
    }
    unsigned int wexcl = __shfl_sync(0xffffffffu, wx - wt, warp);
    unsigned int base = wexcl + (x - tot);
    #pragma unroll
    for (int i = 0; i < 16; i++) l[i] += base;
    hv[0] = make_uint4(l[0], l[1], l[2], l[3]);
    hv[1] = make_uint4(l[4], l[5], l[6], l[7]);
    hv[2] = make_uint4(l[8], l[9], l[10], l[11]);
    hv[3] = make_uint4(l[12], l[13], l[14], l[15]);
    __syncthreads();
}

// exact 0-based rank of record w in bin b: binstart + #(smaller in bin).
// After the atomic scatter, hist[b] = inclusive end of bin b, so
// segment(b) = [hist[b-1] (or 0), hist[b]). Loads are independent (MLP).
__device__ __forceinline__ unsigned int
bin_rank(const Smem* sm, unsigned long long w, int b) {
    unsigned int st = (b == 0) ? 0u : sm->hist[b - 1];
    unsigned int en = sm->hist[b];
    unsigned int cnt = 0;
    for (unsigned int j = st; j < en; j++)
        cnt += (sm->sdata[j] < w);
    return st + cnt;
}

__global__ void __launch_bounds__(NTHREADS, 1)
spearman_fused_kernel(const float* __restrict__ pred, const float* __restrict__ tgt,
                      float* __restrict__ out) {
    extern __shared__ char raw[];
    Smem* sm = (Smem*)raw;

    const int col  = blockIdx.x;
    const int tid  = threadIdx.x;
    const int lane = tid & 31;
    const int warp = tid >> 5;

    // ---- A: zero hist; load pred, histogram, records in regs ----
    zero_hist(sm, tid);
    __syncthreads();

    unsigned long long e[SLOTS];   // pred: key<<32 | row   (row < 2^14)
    int bb[SLOTS];
    #pragma unroll
    for (int s = 0; s < SLOTS; s++) {
        int row = tid + s * NTHREADS;
        float x = pred[(size_t)row * NCOLS + col];
        bb[s] = valbin(x);
        e[s] = ((unsigned long long)f2sort(x) << 32) | (unsigned int)row;
        atomicAdd(&sm->hist[bb[s]], 1u);
    }
    __syncthreads();

    // ---- B: exclusive scan ----
    scan_hist(sm, tid, lane, warp);

    // ---- C: scatter (atomic per-bin offsets; hist becomes bin ends) ----
    #pragma unroll
    for (int s = 0; s < SLOTS; s++) {
        unsigned int pos = atomicAdd(&sm->hist[bb[s]], 1u);
        sm->sdata[pos] = e[s];
    }
    __syncthreads();

    // ---- D: per-element exact pred rank; build target records ----
    #pragma unroll
    for (int s = 0; s < SLOTS; s++) {
        unsigned int rank_p = bin_rank(sm, e[s], bb[s]);   // 0-based
        unsigned int row = (unsigned int)e[s] & 0x3fffu;
        float x = tgt[(size_t)row * NCOLS + col];
        bb[s] = valbin(x);
        e[s] = ((unsigned long long)f2sort(x) << 32)
             | ((unsigned long long)row << 14)
             | (unsigned long long)rank_p;                 // key|row|rank_p
    }
    __syncthreads();   // all bin_rank reads done before hist is re-zeroed

    // ---- E: zero hist; histogram target ----
    zero_hist(sm, tid);
    __syncthreads();
    #pragma unroll
    for (int s = 0; s < SLOTS; s++)
        atomicAdd(&sm->hist[bb[s]], 1u);
    __syncthreads();

    // ---- F: scan ----
    scan_hist(sm, tid, lane, warp);

    // ---- G: scatter target records ----
    #pragma unroll
    for (int s = 0; s < SLOTS; s++) {
        unsigned int pos = atomicAdd(&sm->hist[bb[s]], 1u);
        sm->sdata[pos] = e[s];
    }
    __syncthreads();

    // ---- H: per-element exact target rank -> int64 dot ----
    // ties (equal key) resolve at the unique row field => stable-argsort order
    unsigned long long s64 = 0ull;
    #pragma unroll
    for (int s = 0; s < SLOTS; s++) {
        unsigned int rank_t = bin_rank(sm, e[s], bb[s]);   // 0-based
        unsigned int rank_p = (unsigned int)e[s] & 0x3fffu;
        s64 += (unsigned long long)(rank_t + 1u) * (unsigned long long)(rank_p + 1u);
    }
    #pragma unroll
    for (int o = 16; o > 0; o >>= 1)
        s64 += __shfl_down_sync(0xffffffffu, s64, o);
    if (lane == 0) sm->warp_s[warp] = s64;
    __syncthreads();
    if (warp == 0) {
        s64 = (lane < NWARPS) ? sm->warp_s[lane] : 0ull;
        #pragma unroll
        for (int o = 16; o > 0; o >>= 1)
            s64 += __shfl_down_sync(0xffffffffu, s64, o);
        if (lane == 0) g_part[col] = s64;
    }

    // ---- grid-wide completion: last CTA finalizes ----
    if (tid == 0) {
        __threadfence();
        unsigned int t = atomicAdd(&g_arrive, 1u);
        sm->is_last = (t == (unsigned)(NCOLS - 1));
    }
    __syncthreads();
    if (!sm->is_last) return;

    __threadfence();                 // acquire: all g_part writes visible
    if (tid == 0) g_arrive = 0u;     // reset for next graph replay

    unsigned long long s2 = (tid < NCOLS) ? g_part[tid] : 0ull;
    #pragma unroll
    for (int o = 16; o > 0; o >>= 1)
        s2 += __shfl_down_sync(0xffffffffu, s2, o);
    if (lane == 0) sm->warp_s[warp] = s2;
    __syncthreads();
    if (warp == 0) {
        s2 = (lane < NWARPS) ? sm->warp_s[lane] : 0ull;
        #pragma unroll
        for (int o = 16; o > 0; o >>= 1)
            s2 += __shfl_down_sync(0xffffffffu, s2, o);
        if (lane == 0) {
            const double Nd = (double)NROWS;
            const double Dd = (double)NCOLS;
            const double mu = (Nd + 1.0) * 0.5;
            const double var = (Nd * Nd - 1.0) / 12.0;
            const double sd = sqrt(var + 1e-6);
            const double denom = sd * sd + 1e-6;
            const double mean_pt = (double)s2 / (Nd * Dd);
            const double corr_mean = (mean_pt - mu * mu) / denom;
            out[0] = (float)(-corr_mean);
        }
    }
}

extern "C" void kernel_launch(void* const* d_in, const int* in_sizes, int n_in,
                              void* d_out, int out_size) {
    const float* pred = (const float*)d_in[0];
    const float* tgt  = (const float*)d_in[1];
    float* out = (float*)d_out;

    const int smem_bytes = (int)sizeof(Smem);
    cudaFuncSetAttribute(spearman_fused_kernel,
                         cudaFuncAttributeMaxDynamicSharedMemorySize, smem_bytes);

    spearman_fused_kernel<<<NCOLS, NTHREADS, smem_bytes>>>(pred, tgt, out);
}

// round 17
// speedup vs baseline: 1.6726x; 1.0057x over previous
#include <cuda_runtime.h>
#include <cstdint>

// SpearmanCorrelationLoss: pred/target [N=16384, D=512] fp32.
// Ranks are exact permutations of 1..N => mean/std constants; only need the
// exact int64 sum of rank products.
// Per-column: value-binned grouping (monotone linear binning, 16384 bins,
// atomic scatter of key32/row16) + per-element EXACT rank =
// binstart + #(smaller in bin), scanned with aligned uint4 loads (4 keys per
// LDS.128). Key ties (rare) resolved exactly via srow slow path. Rank_p and
// rows stay register-resident. Single fused kernel; last CTA finalizes.

#define NROWS 16384
#define NCOLS 512
#define NTHREADS 1024
#define NWARPS 32
#define SLOTS 16          // items per thread
#define NB 16384          // value bins
#define BPT (NB / NTHREADS)   // bins per thread = 16

__device__ unsigned long long g_part[NCOLS];
__device__ unsigned int g_arrive;

__device__ __forceinline__ unsigned int f2sort(float f) {
    unsigned int u = __float_as_uint(f);
    return (u & 0x80000000u) ? ~u : (u | 0x80000000u);
}
__device__ __forceinline__ int valbin(float x) {
    // monotone: floor of increasing linear map; clamp to [0, NB-1]
    float t = (x + 5.5f) * (16384.0f / 11.0f);
    int b = __float2int_rd(t);
    return min(max(b, 0), NB - 1);
}

struct __align__(16) Smem {
    unsigned int       skey[NROWS];    // 64 KB (16B aligned for uint4 loads)
    unsigned int       hist[NB];       // 64 KB
    unsigned short     srow[NROWS];    // 32 KB (tie-break only)
    unsigned int       wscan[NWARPS];
    unsigned long long warp_s[NWARPS];
    int                is_last;
};

__device__ __forceinline__ void zero_hist(Smem* sm, int tid) {
    uint4 z = make_uint4(0, 0, 0, 0);
    uint4* hv = (uint4*)(sm->hist + tid * BPT);
    hv[0] = z; hv[1] = z; hv[2] = z; hv[3] = z;
}

// exclusive scan of hist[NB] in place (thread t owns bins [16t,16t+16))
__device__ __forceinline__ void scan_hist(Smem* sm, int tid, int lane, int warp) {
    uint4* hv = (uint4*)(sm->hist + tid * BPT);
    uint4 h0 = hv[0], h1 = hv[1], h2 = hv[2], h3 = hv[3];
    unsigned int l[16] = {h0.x, h0.y, h0.z, h0.w, h1.x, h1.y, h1.z, h1.w,
                          h2.x, h2.y, h2.z, h2.w, h3.x, h3.y, h3.z, h3.w};
    unsigned int tot = 0;
    #pragma unroll
    for (int i = 0; i < 16; i++) { unsigned int v = l[i]; l[i] = tot; tot += v; }
    unsigned int x = tot;
    #pragma unroll
    for (int o = 1; o < 32; o <<= 1) {
        unsigned int y = __shfl_up_sync(0xffffffffu, x, o);
        if (lane >= o) x += y;
    }
    if (lane == 31) sm->wscan[warp] = x;
    __syncthreads();
    unsigned int wt = sm->wscan[lane];
    unsigned int wx = wt;
    #pragma unroll
    for (int o = 1; o < 32; o <<= 1) {
        unsigned int y = __shfl_up_sync(0xffffffffu, wx, o);
        if (lane >= o) wx += y;
    }
    unsigned int wexcl = __shfl_sync(0xffffffffu, wx - wt, warp);
    unsigned int base = wexcl + (x - tot);
    #pragma unroll
    for (int i = 0; i < 16; i++) l[i] += base;
    hv[0] = make_uint4(l[0], l[1], l[2], l[3]);
    hv[1] = make_uint4(l[4], l[5], l[6], l[7]);
    hv[2] = make_uint4(l[8], l[9], l[10], l[11]);
    hv[3] = make_uint4(l[12], l[13], l[14], l[15]);
    __syncthreads();
}

// exact 0-based rank of (k, row) within the grouped array:
// binstart + #(key smaller) + #(key equal with smaller row).
// Bin segment = [hist[b-1] (or 0), hist[b]); scanned 4 keys per LDS.128.
__device__ __forceinline__ unsigned int
bin_rank(const Smem* sm, unsigned int k, unsigned int row, int b) {
    unsigned int st = (b == 0) ? 0u : sm->hist[b - 1];
    unsigned int en = sm->hist[b];
    const uint4* kv4 = (const uint4*)sm->skey;
    unsigned int less = 0, eq = 0;
    for (unsigned int j0 = st & ~3u; j0 < en; j0 += 4) {
        uint4 q = kv4[j0 >> 2];
        unsigned int j;
        j = j0 + 0; if (j >= st && j < en) { less += (q.x < k); eq += (q.x == k); }
        j = j0 + 1; if (j >= st && j < en) { less += (q.y < k); eq += (q.y == k); }
        j = j0 + 2; if (j >= st && j < en) { less += (q.z < k); eq += (q.z == k); }
        j = j0 + 3; if (j >= st && j < en) { less += (q.w < k); eq += (q.w == k); }
    }
    unsigned int r = less;
    if (eq > 1u) {   // rare exact-key tie: resolve by original row (stable)
        for (unsigned int j = st; j < en; j++)
            if (sm->skey[j] == k && sm->srow[j] < row) r++;
    }
    return st + r;
}

__global__ void __launch_bounds__(NTHREADS, 1)
spearman_fused_kernel(const float* __restrict__ pred, const float* __restrict__ tgt,
                      float* __restrict__ out) {
    extern __shared__ char raw[];
    Smem* sm = (Smem*)raw;

    const int col  = blockIdx.x;
    const int tid  = threadIdx.x;
    const int lane = tid & 31;
    const int warp = tid >> 5;

    // ---- A: zero hist; load pred, histogram; keys stay in regs ----
    zero_hist(sm, tid);
    __syncthreads();

    unsigned int kreg[SLOTS];
    int bb[SLOTS];
    #pragma unroll
    for (int s = 0; s < SLOTS; s++) {
        int row = tid + s * NTHREADS;
        float x = pred[(size_t)row * NCOLS + col];
        bb[s] = valbin(x);
        kreg[s] = f2sort(x);
        atomicAdd(&sm->hist[bb[s]], 1u);
    }
    __syncthreads();

    // ---- B: exclusive scan ----
    scan_hist(sm, tid, lane, warp);

    // ---- C: scatter key+row (hist becomes bin ends) ----
    #pragma unroll
    for (int s = 0; s < SLOTS; s++) {
        unsigned int pos = atomicAdd(&sm->hist[bb[s]], 1u);
        sm->skey[pos] = kreg[s];
        sm->srow[pos] = (unsigned short)(tid + s * NTHREADS);
    }
    __syncthreads();

    // ---- D: exact pred rank; load target keys ----
    unsigned int rank_p[SLOTS];
    #pragma unroll
    for (int s = 0; s < SLOTS; s++) {
        int row = tid + s * NTHREADS;
        rank_p[s] = bin_rank(sm, kreg[s], (unsigned int)row, bb[s]);  // 0-based
        float x = tgt[(size_t)row * NCOLS + col];
        bb[s] = valbin(x);
        kreg[s] = f2sort(x);
    }
    __syncthreads();   // all bin_rank reads done before hist reset

    // ---- E: zero hist; histogram target ----
    zero_hist(sm, tid);
    __syncthreads();
    #pragma unroll
    for (int s = 0; s < SLOTS; s++)
        atomicAdd(&sm->hist[bb[s]], 1u);
    __syncthreads();

    // ---- F: scan ----
    scan_hist(sm, tid, lane, warp);

    // ---- G: scatter target key+row ----
    #pragma unroll
    for (int s = 0; s < SLOTS; s++) {
        unsigned int pos = atomicAdd(&sm->hist[bb[s]], 1u);
        sm->skey[pos] = kreg[s];
        sm->srow[pos] = (unsigned short)(tid + s * NTHREADS);
    }
    __syncthreads();

    // ---- H: exact target rank -> int64 dot ----
    unsigned long long s64 = 0ull;
    #pragma unroll
    for (int s = 0; s < SLOTS; s++) {
        int row = tid + s * NTHREADS;
        unsigned int rank_t = bin_rank(sm, kreg[s], (unsigned int)row, bb[s]);
        s64 += (unsigned long long)(rank_t + 1u) * (unsigned long long)(rank_p[s] + 1u);
    }
    #pragma unroll
    for (int o = 16; o > 0; o >>= 1)
        s64 += __shfl_down_sync(0xffffffffu, s64, o);
    if (lane == 0) sm->warp_s[warp] = s64;
    __syncthreads();
    if (warp == 0) {
        s64 = (lane < NWARPS) ? sm->warp_s[lane] : 0ull;
        #pragma unroll
        for (int o = 16; o > 0; o >>= 1)
            s64 += __shfl_down_sync(0xffffffffu, s64, o);
        if (lane == 0) g_part[col] = s64;
    }

    // ---- grid-wide completion: last CTA finalizes ----
    if (tid == 0) {
        __threadfence();
        unsigned int t = atomicAdd(&g_arrive, 1u);
        sm->is_last = (t == (unsigned)(NCOLS - 1));
    }
    __syncthreads();
    if (!sm->is_last) return;

    __threadfence();                 // acquire: all g_part writes visible
    if (tid == 0) g_arrive = 0u;     // reset for next graph replay

    unsigned long long s2 = (tid < NCOLS) ? g_part[tid] : 0ull;
    #pragma unroll
    for (int o = 16; o > 0; o >>= 1)
        s2 += __shfl_down_sync(0xffffffffu, s2, o);
    if (lane == 0) sm->warp_s[warp] = s2;
    __syncthreads();
    if (warp == 0) {
        s2 = (lane < NWARPS) ? sm->warp_s[lane] : 0ull;
        #pragma unroll
        for (int o = 16; o > 0; o >>= 1)
            s2 += __shfl_down_sync(0xffffffffu, s2, o);
        if (lane == 0) {
            const double Nd = (double)NROWS;
            const double Dd = (double)NCOLS;
            const double mu = (Nd + 1.0) * 0.5;
            const double var = (Nd * Nd - 1.0) / 12.0;
            const double sd = sqrt(var + 1e-6);
            const double denom = sd * sd + 1e-6;
            const double mean_pt = (double)s2 / (Nd * Dd);
            const double corr_mean = (mean_pt - mu * mu) / denom;
            out[0] = (float)(-corr_mean);
        }
    }
}

extern "C" void kernel_launch(void* const* d_in, const int* in_sizes, int n_in,
                              void* d_out, int out_size) {
    const float* pred = (const float*)d_in[0];
    const float* tgt  = (const float*)d_in[1];
    float* out = (float*)d_out;

    const int smem_bytes = (int)sizeof(Smem);
    cudaFuncSetAttribute(spearman_fused_kernel,
                         cudaFuncAttributeMaxDynamicSharedMemorySize, smem_bytes);

    spearman_fused_kernel<<<NCOLS, NTHREADS, smem_bytes>>>(pred, tgt, out);
}